// round 6
// baseline (speedup 1.0000x reference)
#include <cuda_runtime.h>
#include <math.h>

#define NN 100
#define CC 32
#define HH 512
#define TT 64
#define BB 16
#define EE 2000
#define HZ 10
#define NC 3200    // NN*CC
#define G4 2048    // 4*HH
#define TB 1024    // TT*BB
#define NBLK 128   // persistent grid size

// ------------------------- device scratch -------------------------
__device__ float g_norm[EE];
__device__ float g_Xin[TB * NC];
__device__ float g_G0[TB * G4];
__device__ float g_G1[TB * G4];
__device__ float g_hs0[(TT + 1) * BB * HH];   // slot 0 never written => zeros
__device__ float g_hs1[(TT + 1) * BB * HH];
__device__ float g_c0[BB * HH];
__device__ float g_c1l[BB * HH];
__device__ float g_dh1s[HZ + 1][BB * HH];
__device__ float g_dh2s[HZ + 1][BB * HH];
__device__ float g_dc1[BB * HH];
__device__ float g_dc2[BB * HH];
__device__ float g_dxins[HZ][BB * NC];
__device__ unsigned g_barctr[3];

__device__ __forceinline__ float geluf(float x) {
    return 0.5f * x * (1.0f + erff(x * 0.70710678118654752f));
}
__device__ __forceinline__ float sigmf(float x) { return 1.0f / (1.0f + expf(-x)); }

// grid barrier: all NBLK blocks co-resident (grid <= #SMs)
__device__ __forceinline__ void gbar(unsigned* ctr, unsigned& tgt) {
    __threadfence();
    __syncthreads();
    if (threadIdx.x == 0) {
        atomicAdd(ctr, 1u);
        while (*(volatile unsigned*)ctr < tgt) { }
    }
    __syncthreads();
    tgt += NBLK;
}

// ------------------------- init / prep -------------------------
__global__ void k_zero() {
    int i = blockIdx.x * blockDim.x + threadIdx.x;
    if (i < BB * HH) { g_c0[i] = 0.f; g_c1l[i] = 0.f; }
    if (i < 3) g_barctr[i] = 0u;
}

__global__ void k_prep(const int* __restrict__ ei, const float* __restrict__ ew) {
    __shared__ float sdeg[NN];
    __shared__ float sdinv[NN];
    int tid = threadIdx.x;
    for (int n = tid; n < NN; n += blockDim.x) sdeg[n] = 0.f;
    __syncthreads();
    for (int e = tid; e < EE; e += blockDim.x) atomicAdd(&sdeg[ei[EE + e]], ew[e]);
    __syncthreads();
    for (int n = tid; n < NN; n += blockDim.x) {
        float d = sdeg[n];
        sdinv[n] = (d > 0.f) ? rsqrtf(fmaxf(d, 1e-12f)) : 0.f;
    }
    __syncthreads();
    for (int e = tid; e < EE; e += blockDim.x)
        g_norm[e] = sdinv[ei[e]] * ew[e] * sdinv[ei[EE + e]];
}

// ------------------------- temporal ARMA + embed -------------------------
__global__ void k_tg(const float* __restrict__ win, const int* __restrict__ ei,
                     const float* __restrict__ tw, const float* __restrict__ tv,
                     const float* __restrict__ tb, const float* __restrict__ emb) {
    __shared__ float s[NN];
    int p = blockIdx.x;
    int base = (p >> 4) * (BB * NN) + (p & 15) * NN;
    int tid = threadIdx.x;
    for (int n = tid; n < NN; n += blockDim.x) s[n] = 0.f;
    __syncthreads();
    for (int e = tid; e < EE; e += blockDim.x)
        atomicAdd(&s[ei[EE + e]], g_norm[e] * win[base + ei[e]]);
    __syncthreads();
    for (int idx = tid; idx < NC; idx += blockDim.x) {
        int n = idx >> 5, c = idx & 31;
        float x = win[base + n];
        float val = geluf(s[n] * tw[c] + x * tv[c] + tb[c]);
        int j = base + n;
        int t2 = j & (TT - 1);
        int rest = j >> 6;
        int n2 = rest % NN, b2 = rest / NN;
        g_Xin[(size_t)(t2 * BB + b2) * NC + n2 * CC + c] = val + emb[n2 * CC + c];
    }
}

// ------------------------- NT SGEMM (M=1024, N=2048) -------------------------
__global__ void k_gemm_nt(int sel, const float* __restrict__ W,
                          const float* __restrict__ b1, const float* __restrict__ b2) {
    const float* A;
    float* Cc;
    int K;
    if (sel == 0) { A = g_Xin; Cc = g_G0; K = NC; }
    else          { A = g_hs0 + BB * HH; Cc = g_G1; K = HH; }

    __shared__ __align__(16) float As[16][128];
    __shared__ __align__(16) float Bs[16][128];
    int tid = threadIdx.x;
    int m0 = blockIdx.y * 128, n0 = blockIdx.x * 128;
    int tm = tid >> 4, tn = tid & 15;
    int li = tid >> 2, lj = (tid & 3) << 2;

    float acc[8][8];
#pragma unroll
    for (int i = 0; i < 8; i++)
#pragma unroll
        for (int j = 0; j < 8; j++) acc[i][j] = 0.f;

    for (int k0 = 0; k0 < K; k0 += 16) {
        float4 a0 = *reinterpret_cast<const float4*>(A + (size_t)(m0 + li) * K + k0 + lj);
        float4 a1 = *reinterpret_cast<const float4*>(A + (size_t)(m0 + li + 64) * K + k0 + lj);
        float4 w0 = *reinterpret_cast<const float4*>(W + (size_t)(n0 + li) * K + k0 + lj);
        float4 w1 = *reinterpret_cast<const float4*>(W + (size_t)(n0 + li + 64) * K + k0 + lj);
        __syncthreads();
        As[lj + 0][li] = a0.x; As[lj + 1][li] = a0.y; As[lj + 2][li] = a0.z; As[lj + 3][li] = a0.w;
        As[lj + 0][li + 64] = a1.x; As[lj + 1][li + 64] = a1.y; As[lj + 2][li + 64] = a1.z; As[lj + 3][li + 64] = a1.w;
        Bs[lj + 0][li] = w0.x; Bs[lj + 1][li] = w0.y; Bs[lj + 2][li] = w0.z; Bs[lj + 3][li] = w0.w;
        Bs[lj + 0][li + 64] = w1.x; Bs[lj + 1][li + 64] = w1.y; Bs[lj + 2][li + 64] = w1.z; Bs[lj + 3][li + 64] = w1.w;
        __syncthreads();
#pragma unroll
        for (int kk = 0; kk < 16; kk++) {
            float ra[8], rb[8];
            *reinterpret_cast<float4*>(&ra[0]) = *reinterpret_cast<float4*>(&As[kk][tm * 8]);
            *reinterpret_cast<float4*>(&ra[4]) = *reinterpret_cast<float4*>(&As[kk][tm * 8 + 4]);
            *reinterpret_cast<float4*>(&rb[0]) = *reinterpret_cast<float4*>(&Bs[kk][tn * 8]);
            *reinterpret_cast<float4*>(&rb[4]) = *reinterpret_cast<float4*>(&Bs[kk][tn * 8 + 4]);
#pragma unroll
            for (int i = 0; i < 8; i++)
#pragma unroll
                for (int j = 0; j < 8; j++) acc[i][j] += ra[i] * rb[j];
        }
    }

    float bias[8];
#pragma unroll
    for (int j = 0; j < 8; j++) bias[j] = b1[n0 + tn * 8 + j] + b2[n0 + tn * 8 + j];
#pragma unroll
    for (int i = 0; i < 8; i++) {
        float* cp = Cc + (size_t)(m0 + tm * 8 + i) * G4 + n0 + tn * 8;
#pragma unroll
        for (int j = 0; j < 8; j++) cp[j] = acc[i][j] + bias[j];
    }
}

// ------------------------- persistent recurrence (one layer, 64 steps) ------
// dyn smem: swhh[16*512] | sh[16*516] | sg[256]
extern __shared__ float dynsm[];

__global__ void __launch_bounds__(256) k_rec(int layer, const float* __restrict__ Whh) {
    float* swhh = dynsm;
    float* sh = dynsm + 16 * 512;
    float* sg = dynsm + 16 * 512 + 16 * 516;
    const float* Gall = (layer == 0) ? g_G0 : g_G1;
    float* hs = (layer == 0) ? g_hs0 : g_hs1;
    float* c_st = (layer == 0) ? g_c0 : g_c1l;
    unsigned* ctr = &g_barctr[layer];

    int tid = threadIdx.x;
    int rowid = tid >> 4, bb = tid & 15;
    int bq = tid >> 4, q = tid & 15;
    int row = (rowid >> 2) * HH + blockIdx.x * 4 + (rowid & 3);

    // cache the block's 16 Whh rows in smem (once for all 64 steps)
    for (int i = tid; i < 16 * 128; i += 256) {
        int r = i >> 7, k4 = (i & 127) << 2;
        int grow = (r >> 2) * HH + blockIdx.x * 4 + (r & 3);
        *reinterpret_cast<float4*>(swhh + r * 512 + k4) =
            *reinterpret_cast<const float4*>(Whh + (size_t)grow * HH + k4);
    }

    unsigned tgt = NBLK;
    for (int t = 0; t < TT; t++) {
        const float* h_in = hs + (size_t)t * BB * HH;
        __syncthreads();
#pragma unroll
        for (int m = 0; m < 8; m++) {
            float4 v = *reinterpret_cast<const float4*>(h_in + bq * HH + m * 64 + q * 4);
            *reinterpret_cast<float4*>(sh + bq * 516 + m * 64 + q * 4) = v;
        }
        __syncthreads();
        const float* w = swhh + rowid * 512;
        const float* hr = sh + bb * 516;
        float a0 = 0.f, a1 = 0.f, a2 = 0.f, a3 = 0.f;
#pragma unroll 16
        for (int k = 0; k < HH; k += 4) {
            float4 wv = *reinterpret_cast<const float4*>(w + k);
            float4 hv = *reinterpret_cast<const float4*>(hr + k);
            a0 += wv.x * hv.x; a1 += wv.y * hv.y; a2 += wv.z * hv.z; a3 += wv.w * hv.w;
        }
        sg[rowid * 16 + bb] = (a0 + a1) + (a2 + a3) +
                              Gall[(size_t)t * BB * G4 + bb * G4 + row];
        __syncthreads();
        if (tid < 64) {
            int jq = tid >> 4, b = tid & 15;
            float iv = sigmf(sg[jq * 16 + b]);
            float fv = sigmf(sg[(4 + jq) * 16 + b]);
            float gv = tanhf(sg[(8 + jq) * 16 + b]);
            float ov = sigmf(sg[(12 + jq) * 16 + b]);
            int idx = b * HH + blockIdx.x * 4 + jq;
            float cn = fv * c_st[idx] + iv * gv;
            c_st[idx] = cn;
            hs[(size_t)(t + 1) * BB * HH + idx] = ov * tanhf(cn);
        }
        if (t < TT - 1) gbar(ctr, tgt);
    }
}

// ------------------------- decoder state seed -------------------------
__global__ void k_copyfin() {
    int i = blockIdx.x * blockDim.x + threadIdx.x;
    if (i < BB * HH) {
        float v0 = g_hs0[(size_t)TT * BB * HH + i];
        g_dh1s[0][i] = v0; g_dc1[i] = v0;
        float v1 = g_hs1[(size_t)TT * BB * HH + i];
        g_dh2s[0][i] = v1; g_dc2[i] = v1;
    }
}

// ------------------------- decoder LSTM cell (device) -------------------------
__device__ __forceinline__ void cellstep(
    const float* __restrict__ x, int Kx,
    const float* __restrict__ h_in, float* __restrict__ h_out,
    float* __restrict__ c_st,
    const float* __restrict__ Wih, const float* __restrict__ Whh,
    const float* __restrict__ bih, const float* __restrict__ bhh,
    float* s_x, float* s_g)
{
    int tid = threadIdx.x;
    int rowid = tid >> 4, bb = tid & 15;
    int bq = tid >> 4, q = tid & 15;
    int row = (rowid >> 2) * HH + blockIdx.x * 4 + (rowid & 3);
    float a0 = 0.f, a1 = 0.f, a2 = 0.f, a3 = 0.f;

    for (int k0 = 0; k0 < Kx; k0 += 512) {
        int len = min(512, Kx - k0);
        __syncthreads();
        for (int m = 0; m * 64 < len; m++) {
            float4 v = *reinterpret_cast<const float4*>(x + (size_t)bq * Kx + k0 + m * 64 + q * 4);
            *reinterpret_cast<float4*>(s_x + bq * 516 + m * 64 + q * 4) = v;
        }
        __syncthreads();
        const float* w = Wih + (size_t)row * Kx + k0;
        const float* hr = s_x + bb * 516;
#pragma unroll 8
        for (int k = 0; k < len; k += 4) {
            float4 wv = *reinterpret_cast<const float4*>(w + k);
            float4 hv = *reinterpret_cast<const float4*>(hr + k);
            a0 += wv.x * hv.x; a1 += wv.y * hv.y; a2 += wv.z * hv.z; a3 += wv.w * hv.w;
        }
    }

    __syncthreads();
#pragma unroll
    for (int m = 0; m < 8; m++) {
        float4 v = *reinterpret_cast<const float4*>(h_in + bq * HH + m * 64 + q * 4);
        *reinterpret_cast<float4*>(s_x + bq * 516 + m * 64 + q * 4) = v;
    }
    __syncthreads();
    {
        const float* w = Whh + (size_t)row * HH;
        const float* hr = s_x + bb * 516;
#pragma unroll 8
        for (int k = 0; k < HH; k += 4) {
            float4 wv = *reinterpret_cast<const float4*>(w + k);
            float4 hv = *reinterpret_cast<const float4*>(hr + k);
            a0 += wv.x * hv.x; a1 += wv.y * hv.y; a2 += wv.z * hv.z; a3 += wv.w * hv.w;
        }
    }
    s_g[rowid * 16 + bb] = (a0 + a1) + (a2 + a3) + bih[row] + bhh[row];
    __syncthreads();
    if (tid < 64) {
        int jq = tid >> 4, b = tid & 15;
        float iv = sigmf(s_g[jq * 16 + b]);
        float fv = sigmf(s_g[(4 + jq) * 16 + b]);
        float gv = tanhf(s_g[(8 + jq) * 16 + b]);
        float ov = sigmf(s_g[(12 + jq) * 16 + b]);
        int idx = b * HH + blockIdx.x * 4 + jq;
        float cn = fv * c_st[idx] + iv * gv;
        c_st[idx] = cn;
        h_out[idx] = ov * tanhf(cn);
    }
}

// ------------------------- persistent decoder (all 10 horizon steps) --------
__global__ void __launch_bounds__(256) k_dec(
    const float* __restrict__ Wp, const float* __restrict__ bp,
    const int* __restrict__ ei,
    const float* __restrict__ gw, const float* __restrict__ gv,
    const float* __restrict__ gb, const float* __restrict__ emb,
    const float* __restrict__ c1Wih, const float* __restrict__ c1Whh,
    const float* __restrict__ c1bih, const float* __restrict__ c1bhh,
    const float* __restrict__ c2Wih, const float* __restrict__ c2Whh,
    const float* __restrict__ c2bih, const float* __restrict__ c2bhh,
    float* __restrict__ out)
{
    __shared__ float s_x[16 * 516];
    __shared__ float s_g[256];
    __shared__ float s_h2[HH];
    __shared__ float s_pred[NN];
    __shared__ float s_ss[NN];
    unsigned* ctr = &g_barctr[2];
    unsigned tgt = NBLK;
    int tid = threadIdx.x;

    for (int h = 0; h < HZ; h++) {
        // phase A: pred + ARMA + xin (16 blocks, one per batch)
        if (blockIdx.x < BB) {
            int b = blockIdx.x;
            const float* h2 = g_dh2s[h];
            for (int i = tid; i < HH; i += 256) s_h2[i] = h2[b * HH + i];
            for (int i = tid; i < NN; i += 256) s_ss[i] = 0.f;
            __syncthreads();
            for (int n = tid; n < NN; n += 256) {
                const float* wr = Wp + (size_t)n * HH;
                float d0 = 0.f, d1 = 0.f, d2 = 0.f, d3 = 0.f;
#pragma unroll 8
                for (int k = 0; k < HH; k += 4) {
                    float4 wv = *reinterpret_cast<const float4*>(wr + k);
                    d0 += wv.x * s_h2[k]; d1 += wv.y * s_h2[k + 1];
                    d2 += wv.z * s_h2[k + 2]; d3 += wv.w * s_h2[k + 3];
                }
                float d = (d0 + d1) + (d2 + d3) + bp[n];
                s_pred[n] = d;
                out[(b * NN + n) * HZ + h] = d;
            }
            __syncthreads();
            for (int e = tid; e < EE; e += 256)
                atomicAdd(&s_ss[ei[EE + e]], g_norm[e] * s_pred[ei[e]]);
            __syncthreads();
            for (int idx = tid; idx < NC; idx += 256) {
                int n = idx >> 5, c = idx & 31;
                float val = geluf(s_ss[n] * gw[c] + s_pred[n] * gv[c] + gb[c]);
                g_dxins[h][(size_t)b * NC + idx] = val + emb[idx];
            }
        }
        gbar(ctr, tgt);
        // phase B: cell 1 (K = 3200)
        cellstep(g_dxins[h], NC, g_dh1s[h], g_dh1s[h + 1], g_dc1,
                 c1Wih, c1Whh, c1bih, c1bhh, s_x, s_g);
        gbar(ctr, tgt);
        // phase C: cell 2 (K = 512)
        cellstep(g_dh1s[h + 1], HH, g_dh2s[h], g_dh2s[h + 1], g_dc2,
                 c2Wih, c2Whh, c2bih, c2bhh, s_x, s_g);
        if (h < HZ - 1) gbar(ctr, tgt);
    }
}

// ------------------------- launch -------------------------
extern "C" void kernel_launch(void* const* d_in, const int* in_sizes, int n_in,
                              void* d_out, int out_size) {
    const float* window = (const float*)d_in[0];
    const int*   ei     = (const int*)d_in[1];
    const float* ew     = (const float*)d_in[2];
    const float* emb    = (const float*)d_in[3];
    const float* tg_w   = (const float*)d_in[4];
    const float* tg_v   = (const float*)d_in[5];
    const float* tg_b   = (const float*)d_in[6];
    const float* gnn_w  = (const float*)d_in[7];
    const float* gnn_v  = (const float*)d_in[8];
    const float* gnn_b  = (const float*)d_in[9];
    const float* Wih0   = (const float*)d_in[10];
    const float* Whh0   = (const float*)d_in[11];
    const float* bih0   = (const float*)d_in[12];
    const float* bhh0   = (const float*)d_in[13];
    const float* Wih1   = (const float*)d_in[14];
    const float* Whh1   = (const float*)d_in[15];
    const float* bih1   = (const float*)d_in[16];
    const float* bhh1   = (const float*)d_in[17];
    const float* c1Wih  = (const float*)d_in[18];
    const float* c1Whh  = (const float*)d_in[19];
    const float* c1bih  = (const float*)d_in[20];
    const float* c1bhh  = (const float*)d_in[21];
    const float* c2Wih  = (const float*)d_in[22];
    const float* c2Whh  = (const float*)d_in[23];
    const float* c2bih  = (const float*)d_in[24];
    const float* c2bhh  = (const float*)d_in[25];
    const float* Wp     = (const float*)d_in[26];
    const float* bp     = (const float*)d_in[27];
    float* out = (float*)d_out;

    const int REC_SMEM = (16 * 512 + 16 * 516 + 256) * 4;   // 66816 B
    cudaFuncSetAttribute(k_rec, cudaFuncAttributeMaxDynamicSharedMemorySize, REC_SMEM);

    k_zero<<<32, 256>>>();
    k_prep<<<1, 256>>>(ei, ew);
    k_tg<<<TB, 256>>>(window, ei, tg_w, tg_v, tg_b, emb);

    dim3 gg(G4 / 128, TB / 128);
    k_gemm_nt<<<gg, 256>>>(0, Wih0, bih0, bhh0);
    k_rec<<<NBLK, 256, REC_SMEM>>>(0, Whh0);
    k_gemm_nt<<<gg, 256>>>(1, Wih1, bih1, bhh1);
    k_rec<<<NBLK, 256, REC_SMEM>>>(1, Whh1);

    k_copyfin<<<32, 256>>>();
    k_dec<<<NBLK, 256>>>(Wp, bp, ei, gnn_w, gnn_v, gnn_b, emb,
                         c1Wih, c1Whh, c1bih, c1bhh,
                         c2Wih, c2Whh, c2bih, c2bhh, out);
    (void)in_sizes; (void)n_in; (void)out_size;
}

// round 7
// speedup vs baseline: 1.7931x; 1.7931x over previous
#include <cuda_runtime.h>
#include <math.h>
typedef unsigned long long ull;

#define NN 100
#define CC 32
#define HH 512
#define TT 64
#define BB 16
#define EE 2000
#define HZ 10
#define NC 3200
#define G4 2048
#define TB 1024
#define NBLK 128

__device__ float g_norm[EE];
__device__ float g_Xin[TB * NC];
__device__ float g_G0[TB * G4];
__device__ float g_G1[TB * G4];
__device__ float g_hs0[(TT + 1) * BB * HH];   // slot 0 stays zero
__device__ float g_hs1[(TT + 1) * BB * HH];
__device__ float g_dh1s[HZ + 1][BB * HH];
__device__ float g_dh2s[HZ + 1][BB * HH];
__device__ float g_dxins[HZ][BB * NC];
__device__ unsigned g_barctr[3];

__device__ __forceinline__ float geluf(float x) {
    return 0.5f * x * (1.0f + erff(x * 0.70710678118654752f));
}
__device__ __forceinline__ float sigmf(float x) { return 1.0f / (1.0f + expf(-x)); }

__device__ __forceinline__ ull pk2(float lo, float hi) {
    ull r; asm("mov.b64 %0, {%1, %2};" : "=l"(r) : "f"(lo), "f"(hi)); return r;
}
__device__ __forceinline__ float2 upk2(ull v) {
    float2 r; asm("mov.b64 {%0, %1}, %2;" : "=f"(r.x), "=f"(r.y) : "l"(v)); return r;
}
__device__ __forceinline__ ull ffma2(ull a, ull b, ull c) {
    ull d; asm("fma.rn.f32x2 %0, %1, %2, %3;" : "=l"(d) : "l"(a), "l"(b), "l"(c));
    return d;
}
__device__ __forceinline__ float sum2(ull v) { float2 u = upk2(v); return u.x + u.y; }

__device__ __forceinline__ void gbar(unsigned* ctr, unsigned& tgt) {
    __threadfence();
    __syncthreads();
    if (threadIdx.x == 0) {
        atomicAdd(ctr, 1u);
        while (*(volatile unsigned*)ctr < tgt) { }
    }
    __syncthreads();
    tgt += NBLK;
}

__global__ void k_zero() {
    int i = blockIdx.x * blockDim.x + threadIdx.x;
    if (i < 3) g_barctr[i] = 0u;
}

__global__ void k_prep(const int* __restrict__ ei, const float* __restrict__ ew) {
    __shared__ float sdeg[NN], sdinv[NN];
    int tid = threadIdx.x;
    for (int n = tid; n < NN; n += blockDim.x) sdeg[n] = 0.f;
    __syncthreads();
    for (int e = tid; e < EE; e += blockDim.x) atomicAdd(&sdeg[ei[EE + e]], ew[e]);
    __syncthreads();
    for (int n = tid; n < NN; n += blockDim.x) {
        float d = sdeg[n];
        sdinv[n] = (d > 0.f) ? rsqrtf(fmaxf(d, 1e-12f)) : 0.f;
    }
    __syncthreads();
    for (int e = tid; e < EE; e += blockDim.x)
        g_norm[e] = sdinv[ei[e]] * ew[e] * sdinv[ei[EE + e]];
}

__global__ void k_tg(const float* __restrict__ win, const int* __restrict__ ei,
                     const float* __restrict__ tw, const float* __restrict__ tv,
                     const float* __restrict__ tb, const float* __restrict__ emb) {
    __shared__ float s[NN];
    int p = blockIdx.x;
    int base = (p >> 4) * (BB * NN) + (p & 15) * NN;
    int tid = threadIdx.x;
    for (int n = tid; n < NN; n += blockDim.x) s[n] = 0.f;
    __syncthreads();
    for (int e = tid; e < EE; e += blockDim.x)
        atomicAdd(&s[ei[EE + e]], g_norm[e] * win[base + ei[e]]);
    __syncthreads();
    for (int idx = tid; idx < NC; idx += blockDim.x) {
        int n = idx >> 5, c = idx & 31;
        float x = win[base + n];
        float val = geluf(s[n] * tw[c] + x * tv[c] + tb[c]);
        int j = base + n;
        int t2 = j & (TT - 1);
        int rest = j >> 6;
        int n2 = rest % NN, b2 = rest / NN;
        g_Xin[(size_t)(t2 * BB + b2) * NC + n2 * CC + c] = val + emb[n2 * CC + c];
    }
}

// ---------------- NT GEMM, packed f32x2 (pairs along m) ----------------
__global__ void __launch_bounds__(256) k_gemm_nt(int sel, const float* __restrict__ W,
                          const float* __restrict__ b1, const float* __restrict__ b2) {
    const float* A; float* Cc; int K;
    if (sel == 0) { A = g_Xin; Cc = g_G0; K = NC; }
    else          { A = g_hs0 + BB * HH; Cc = g_G1; K = HH; }

    __shared__ __align__(16) float As[16][128];
    __shared__ __align__(16) float Bs[16][128];
    int tid = threadIdx.x;
    int m0 = blockIdx.y * 128, n0 = blockIdx.x * 128;
    int tm = tid >> 4, tn = tid & 15;
    int li = tid >> 2, lj = (tid & 3) << 2;

    ull acc[4][8];
#pragma unroll
    for (int p = 0; p < 4; p++)
#pragma unroll
        for (int j = 0; j < 8; j++) acc[p][j] = 0ull;

    for (int k0 = 0; k0 < K; k0 += 16) {
        float4 a0 = *reinterpret_cast<const float4*>(A + (size_t)(m0 + li) * K + k0 + lj);
        float4 a1 = *reinterpret_cast<const float4*>(A + (size_t)(m0 + li + 64) * K + k0 + lj);
        float4 w0 = *reinterpret_cast<const float4*>(W + (size_t)(n0 + li) * K + k0 + lj);
        float4 w1 = *reinterpret_cast<const float4*>(W + (size_t)(n0 + li + 64) * K + k0 + lj);
        __syncthreads();
        As[lj + 0][li] = a0.x; As[lj + 1][li] = a0.y; As[lj + 2][li] = a0.z; As[lj + 3][li] = a0.w;
        As[lj + 0][li + 64] = a1.x; As[lj + 1][li + 64] = a1.y; As[lj + 2][li + 64] = a1.z; As[lj + 3][li + 64] = a1.w;
        Bs[lj + 0][li] = w0.x; Bs[lj + 1][li] = w0.y; Bs[lj + 2][li] = w0.z; Bs[lj + 3][li] = w0.w;
        Bs[lj + 0][li + 64] = w1.x; Bs[lj + 1][li + 64] = w1.y; Bs[lj + 2][li + 64] = w1.z; Bs[lj + 3][li + 64] = w1.w;
        __syncthreads();
#pragma unroll
        for (int kk = 0; kk < 16; kk++) {
            const ull* pa = reinterpret_cast<const ull*>(&As[kk][tm * 8]);
            ull ra2[4];
#pragma unroll
            for (int p = 0; p < 4; p++) ra2[p] = pa[p];
            float rb[8];
            *reinterpret_cast<float4*>(&rb[0]) = *reinterpret_cast<float4*>(&Bs[kk][tn * 8]);
            *reinterpret_cast<float4*>(&rb[4]) = *reinterpret_cast<float4*>(&Bs[kk][tn * 8 + 4]);
#pragma unroll
            for (int j = 0; j < 8; j++) {
                ull bj = pk2(rb[j], rb[j]);
#pragma unroll
                for (int p = 0; p < 4; p++) acc[p][j] = ffma2(ra2[p], bj, acc[p][j]);
            }
        }
    }

    float bias[8];
#pragma unroll
    for (int j = 0; j < 8; j++) bias[j] = b1[n0 + tn * 8 + j] + b2[n0 + tn * 8 + j];
#pragma unroll
    for (int p = 0; p < 4; p++) {
        float* cp0 = Cc + (size_t)(m0 + tm * 8 + 2 * p) * G4 + n0 + tn * 8;
        float* cp1 = cp0 + G4;
#pragma unroll
        for (int j = 0; j < 8; j++) {
            float2 v = upk2(acc[p][j]);
            cp0[j] = v.x + bias[j];
            cp1[j] = v.y + bias[j];
        }
    }
}

// ---------------- shared LSTM-cell machinery ----------------
// roles: rp=tid>>5 owns local rows {2rp,2rp+1}; bs=(tid>>4)&1 owns batches bs*8..+7;
// ks=tid&15 owns k float4-slices {ks,16+ks,...}. Conflict-free per LDS.128 phase.
__device__ __forceinline__ int growl(int l, int bx) {
    return (l >> 2) * HH + bx * 4 + (l & 3);
}

// accumulate x[16 x Kx] * W rows into acc, chunked by 512
__device__ __forceinline__ void cell_dot(const float* __restrict__ x, int Kx,
                                         const float* __restrict__ W,
                                         float* sh, int bx, ull acc[2][8]) {
    int tid = threadIdx.x;
    int rp = tid >> 5, bs = (tid >> 4) & 1, ks = tid & 15;
    int b2 = tid >> 4, q = tid & 15;
    for (int k0 = 0; k0 < Kx; k0 += 512) {
        int len = min(512, Kx - k0);
        int m4 = len >> 6;                     // float4 groups of 16 per row
        __syncthreads();
        for (int m = 0; m < m4; m++)
            reinterpret_cast<float4*>(sh + b2 * 512)[m * 16 + q] =
                reinterpret_cast<const float4*>(x + (size_t)b2 * Kx + k0)[m * 16 + q];
        __syncthreads();
        ull wc[2][16];
#pragma unroll 2
        for (int r = 0; r < 2; r++) {
            const float* wp = W + (size_t)growl(rp * 2 + r, bx) * Kx + k0;
            for (int i = 0; i < m4; i++) {
                const ull* pw = reinterpret_cast<const ull*>(wp + (i * 16 + ks) * 4);
                wc[r][2 * i] = pw[0]; wc[r][2 * i + 1] = pw[1];
            }
        }
#pragma unroll 8
        for (int bl = 0; bl < 8; bl++) {
            const float4* row = reinterpret_cast<const float4*>(sh + (bs * 8 + bl) * 512);
            for (int i = 0; i < m4; i++) {
                float4 hv = row[i * 16 + ks];
                ull h0 = pk2(hv.x, hv.y), h1 = pk2(hv.z, hv.w);
                acc[0][bl] = ffma2(wc[0][2 * i], h0, acc[0][bl]);
                acc[0][bl] = ffma2(wc[0][2 * i + 1], h1, acc[0][bl]);
                acc[1][bl] = ffma2(wc[1][2 * i], h0, acc[1][bl]);
                acc[1][bl] = ffma2(wc[1][2 * i + 1], h1, acc[1][bl]);
            }
        }
    }
}

// reduce over 16 ks lanes, add gate preloads, activate, update c, write h
__device__ __forceinline__ void cell_fin(ull acc[2][8], float* sg, int bx,
                                         const float gpre[4], float& creg,
                                         float* __restrict__ h_out) {
    int tid = threadIdx.x;
    int rp = tid >> 5, bs = (tid >> 4) & 1, ks = tid & 15;
    float v[16];
#pragma unroll
    for (int r = 0; r < 2; r++)
#pragma unroll
        for (int bl = 0; bl < 8; bl++) v[r * 8 + bl] = sum2(acc[r][bl]);
#pragma unroll
    for (int d = 1; d < 16; d <<= 1)
#pragma unroll
        for (int i = 0; i < 16; i++) v[i] += __shfl_xor_sync(0xffffffffu, v[i], d);
    sg[(rp * 2 + (ks >> 3)) * 17 + bs * 8 + (ks & 7)] = v[ks];
    __syncthreads();
    if (tid < 64) {
        int jq = tid >> 4, b = tid & 15;
        float gi = sg[jq * 17 + b] + gpre[0];
        float gf = sg[(4 + jq) * 17 + b] + gpre[1];
        float gg = sg[(8 + jq) * 17 + b] + gpre[2];
        float go = sg[(12 + jq) * 17 + b] + gpre[3];
        float cn = sigmf(gf) * creg + sigmf(gi) * tanhf(gg);
        creg = cn;
        h_out[b * HH + bx * 4 + jq] = sigmf(go) * tanhf(cn);
    }
}

// ---------------- persistent recurrence: Whh in registers ----------------
__global__ void __launch_bounds__(256) k_rec(int layer, const float* __restrict__ Whh) {
    __shared__ float sh[16 * 512];
    __shared__ float sg[16 * 17];
    const float* Gall = (layer == 0) ? g_G0 : g_G1;
    float* hs = (layer == 0) ? g_hs0 : g_hs1;
    unsigned* ctr = &g_barctr[layer];
    int tid = threadIdx.x, bx = blockIdx.x;
    int rp = tid >> 5, bs = (tid >> 4) & 1, ks = tid & 15;

    ull w[2][16];
#pragma unroll 2
    for (int r = 0; r < 2; r++) {
        const float* wp = Whh + (size_t)growl(rp * 2 + r, bx) * HH;
#pragma unroll
        for (int i = 0; i < 8; i++) {
            const ull* pw = reinterpret_cast<const ull*>(wp + (i * 16 + ks) * 4);
            w[r][2 * i] = pw[0]; w[r][2 * i + 1] = pw[1];
        }
    }
    float creg = 0.f;
    unsigned tgt = NBLK;

    for (int t = 0; t < TT; t++) {
        const float* h_in = hs + (size_t)t * BB * HH;
        float gpre[4] = {0.f, 0.f, 0.f, 0.f};
        if (tid < 64) {
            const float* Gt = Gall + (size_t)t * BB * G4 + (tid & 15) * G4 + bx * 4 + (tid >> 4);
            gpre[0] = Gt[0]; gpre[1] = Gt[HH]; gpre[2] = Gt[2 * HH]; gpre[3] = Gt[3 * HH];
        }
        __syncthreads();
#pragma unroll
        for (int i = 0; i < 8; i++)
            reinterpret_cast<float4*>(sh)[tid + i * 256] =
                reinterpret_cast<const float4*>(h_in)[tid + i * 256];
        __syncthreads();

        ull acc[2][8];
#pragma unroll
        for (int bl = 0; bl < 8; bl++) { acc[0][bl] = 0ull; acc[1][bl] = 0ull; }
        const float4* base = reinterpret_cast<const float4*>(sh + (bs * 8) * 512);
#pragma unroll 8
        for (int bl = 0; bl < 8; bl++) {
            const float4* row = base + bl * 128;
#pragma unroll
            for (int i = 0; i < 8; i++) {
                float4 hv = row[i * 16 + ks];
                ull h0 = pk2(hv.x, hv.y), h1 = pk2(hv.z, hv.w);
                acc[0][bl] = ffma2(w[0][2 * i], h0, acc[0][bl]);
                acc[0][bl] = ffma2(w[0][2 * i + 1], h1, acc[0][bl]);
                acc[1][bl] = ffma2(w[1][2 * i], h0, acc[1][bl]);
                acc[1][bl] = ffma2(w[1][2 * i + 1], h1, acc[1][bl]);
            }
        }
        cell_fin(acc, sg, bx, gpre, creg, hs + (size_t)(t + 1) * BB * HH);
        if (t < TT - 1) gbar(ctr, tgt);
    }
}

__global__ void k_copyfin() {
    int i = blockIdx.x * blockDim.x + threadIdx.x;
    if (i < BB * HH) {
        g_dh1s[0][i] = g_hs0[(size_t)TT * BB * HH + i];
        g_dh2s[0][i] = g_hs1[(size_t)TT * BB * HH + i];
    }
}

// ---------------- persistent decoder ----------------
__global__ void __launch_bounds__(256) k_dec(
    const float* __restrict__ Wp, const float* __restrict__ bp,
    const int* __restrict__ ei,
    const float* __restrict__ gw, const float* __restrict__ gv,
    const float* __restrict__ gb, const float* __restrict__ emb,
    const float* __restrict__ c1Wih, const float* __restrict__ c1Whh,
    const float* __restrict__ c1bih, const float* __restrict__ c1bhh,
    const float* __restrict__ c2Wih, const float* __restrict__ c2Whh,
    const float* __restrict__ c2bih, const float* __restrict__ c2bhh,
    float* __restrict__ out)
{
    __shared__ float s_x[16 * 512];
    __shared__ float s_g[16 * 17];
    __shared__ float s_h2[HH];
    __shared__ float s_pred[NN];
    __shared__ float s_ss[NN];
    unsigned* ctr = &g_barctr[2];
    unsigned tgt = NBLK;
    int tid = threadIdx.x, bx = blockIdx.x;

    float c1reg = 0.f, c2reg = 0.f;
    float b1pre[4], b2pre[4];
    if (tid < 64) {
        int jq = tid >> 4, b = tid & 15;
        int idx = b * HH + bx * 4 + jq;
        c1reg = g_hs0[(size_t)TT * BB * HH + idx];   // cell seeded from hidden
        c2reg = g_hs1[(size_t)TT * BB * HH + idx];
#pragma unroll
        for (int g = 0; g < 4; g++) {
            int row = g * HH + bx * 4 + jq;
            b1pre[g] = c1bih[row] + c1bhh[row];
            b2pre[g] = c2bih[row] + c2bhh[row];
        }
    }

    for (int h = 0; h < HZ; h++) {
        // phase A: pred + ARMA + xin (blocks 0..15, one per batch)
        if (bx < BB) {
            const float* h2 = g_dh2s[h];
            for (int i = tid; i < HH; i += 256) s_h2[i] = h2[bx * HH + i];
            for (int i = tid; i < NN; i += 256) s_ss[i] = 0.f;
            __syncthreads();
            for (int n = tid; n < NN; n += 256) {
                const float* wr = Wp + (size_t)n * HH;
                float d0 = 0.f, d1 = 0.f, d2 = 0.f, d3 = 0.f;
#pragma unroll 8
                for (int k = 0; k < HH; k += 4) {
                    float4 wv = *reinterpret_cast<const float4*>(wr + k);
                    d0 += wv.x * s_h2[k]; d1 += wv.y * s_h2[k + 1];
                    d2 += wv.z * s_h2[k + 2]; d3 += wv.w * s_h2[k + 3];
                }
                float d = (d0 + d1) + (d2 + d3) + bp[n];
                s_pred[n] = d;
                out[(bx * NN + n) * HZ + h] = d;
            }
            __syncthreads();
            for (int e = tid; e < EE; e += 256)
                atomicAdd(&s_ss[ei[EE + e]], g_norm[e] * s_pred[ei[e]]);
            __syncthreads();
            for (int idx = tid; idx < NC; idx += 256) {
                int n = idx >> 5, c = idx & 31;
                float val = geluf(s_ss[n] * gw[c] + s_pred[n] * gv[c] + gb[c]);
                g_dxins[h][(size_t)bx * NC + idx] = val + emb[idx];
            }
            __syncthreads();
        }
        gbar(ctr, tgt);
        // phase B: cell 1
        {
            ull acc[2][8];
#pragma unroll
            for (int bl = 0; bl < 8; bl++) { acc[0][bl] = 0ull; acc[1][bl] = 0ull; }
            cell_dot(g_dxins[h], NC, c1Wih, s_x, bx, acc);
            cell_dot(g_dh1s[h], HH, c1Whh, s_x, bx, acc);
            cell_fin(acc, s_g, bx, b1pre, c1reg, g_dh1s[h + 1]);
        }
        gbar(ctr, tgt);
        // phase C: cell 2
        {
            ull acc[2][8];
#pragma unroll
            for (int bl = 0; bl < 8; bl++) { acc[0][bl] = 0ull; acc[1][bl] = 0ull; }
            cell_dot(g_dh1s[h + 1], HH, c2Wih, s_x, bx, acc);
            cell_dot(g_dh2s[h], HH, c2Whh, s_x, bx, acc);
            cell_fin(acc, s_g, bx, b2pre, c2reg, g_dh2s[h + 1]);
        }
        if (h < HZ - 1) gbar(ctr, tgt);
    }
}

extern "C" void kernel_launch(void* const* d_in, const int* in_sizes, int n_in,
                              void* d_out, int out_size) {
    const float* window = (const float*)d_in[0];
    const int*   ei     = (const int*)d_in[1];
    const float* ew     = (const float*)d_in[2];
    const float* emb    = (const float*)d_in[3];
    const float* tg_w   = (const float*)d_in[4];
    const float* tg_v   = (const float*)d_in[5];
    const float* tg_b   = (const float*)d_in[6];
    const float* gnn_w  = (const float*)d_in[7];
    const float* gnn_v  = (const float*)d_in[8];
    const float* gnn_b  = (const float*)d_in[9];
    const float* Wih0   = (const float*)d_in[10];
    const float* Whh0   = (const float*)d_in[11];
    const float* bih0   = (const float*)d_in[12];
    const float* bhh0   = (const float*)d_in[13];
    const float* Wih1   = (const float*)d_in[14];
    const float* Whh1   = (const float*)d_in[15];
    const float* bih1   = (const float*)d_in[16];
    const float* bhh1   = (const float*)d_in[17];
    const float* c1Wih  = (const float*)d_in[18];
    const float* c1Whh  = (const float*)d_in[19];
    const float* c1bih  = (const float*)d_in[20];
    const float* c1bhh  = (const float*)d_in[21];
    const float* c2Wih  = (const float*)d_in[22];
    const float* c2Whh  = (const float*)d_in[23];
    const float* c2bih  = (const float*)d_in[24];
    const float* c2bhh  = (const float*)d_in[25];
    const float* Wp     = (const float*)d_in[26];
    const float* bp     = (const float*)d_in[27];
    float* out = (float*)d_out;

    k_zero<<<1, 32>>>();
    k_prep<<<1, 256>>>(ei, ew);
    k_tg<<<TB, 256>>>(window, ei, tg_w, tg_v, tg_b, emb);

    dim3 gg(G4 / 128, TB / 128);
    k_gemm_nt<<<gg, 256>>>(0, Wih0, bih0, bhh0);
    k_rec<<<NBLK, 256>>>(0, Whh0);
    k_gemm_nt<<<gg, 256>>>(1, Wih1, bih1, bhh1);
    k_rec<<<NBLK, 256>>>(1, Whh1);

    k_copyfin<<<32, 256>>>();
    k_dec<<<NBLK, 256>>>(Wp, bp, ei, gnn_w, gnn_v, gnn_b, emb,
                         c1Wih, c1Whh, c1bih, c1bhh,
                         c2Wih, c2Whh, c2bih, c2bhh, out);
    (void)in_sizes; (void)n_in; (void)out_size;
}

// round 8
// speedup vs baseline: 2.0962x; 1.1691x over previous
#include <cuda_runtime.h>
#include <math.h>
typedef unsigned long long ull;
typedef unsigned int uint32;

#define NN 100
#define CC 32
#define HH 512
#define TT 64
#define BB 16
#define EE 2000
#define HZ 10
#define NC 3200
#define G4 2048
#define TB 1024
#define NBLK 128

__device__ float g_norm[EE];
__device__ float g_Xin[TB * NC];
__device__ float g_G0[TB * G4];
__device__ float g_G1[TB * G4];
__device__ float g_hs0[(TT + 1) * BB * HH];   // slot 0 stays zero
__device__ float g_hs1[(TT + 1) * BB * HH];
__device__ float g_dh1s[HZ + 1][BB * HH];
__device__ float g_dh2s[HZ + 1][BB * HH];
__device__ float g_dxins[HZ][BB * NC];
__device__ unsigned g_barctr[3];

__device__ __forceinline__ float geluf(float x) {
    return 0.5f * x * (1.0f + erff(x * 0.70710678118654752f));
}
__device__ __forceinline__ float sigmf(float x) { return 1.0f / (1.0f + expf(-x)); }

__device__ __forceinline__ ull pk2(float lo, float hi) {
    ull r; asm("mov.b64 %0, {%1, %2};" : "=l"(r) : "f"(lo), "f"(hi)); return r;
}
__device__ __forceinline__ float2 upk2(ull v) {
    float2 r; asm("mov.b64 {%0, %1}, %2;" : "=f"(r.x), "=f"(r.y) : "l"(v)); return r;
}
__device__ __forceinline__ ull ffma2(ull a, ull b, ull c) {
    ull d; asm("fma.rn.f32x2 %0, %1, %2, %3;" : "=l"(d) : "l"(a), "l"(b), "l"(c));
    return d;
}
__device__ __forceinline__ float sum2(ull v) { float2 u = upk2(v); return u.x + u.y; }

__device__ __forceinline__ void gbar(unsigned* ctr, unsigned& tgt) {
    __threadfence();
    __syncthreads();
    if (threadIdx.x == 0) {
        atomicAdd(ctr, 1u);
        while (*(volatile unsigned*)ctr < tgt) { }
    }
    __syncthreads();
    tgt += NBLK;
}

__global__ void k_zero() {
    int i = blockIdx.x * blockDim.x + threadIdx.x;
    if (i < 3) g_barctr[i] = 0u;
}

__global__ void k_prep(const int* __restrict__ ei, const float* __restrict__ ew) {
    __shared__ float sdeg[NN], sdinv[NN];
    int tid = threadIdx.x;
    for (int n = tid; n < NN; n += blockDim.x) sdeg[n] = 0.f;
    __syncthreads();
    for (int e = tid; e < EE; e += blockDim.x) atomicAdd(&sdeg[ei[EE + e]], ew[e]);
    __syncthreads();
    for (int n = tid; n < NN; n += blockDim.x) {
        float d = sdeg[n];
        sdinv[n] = (d > 0.f) ? rsqrtf(fmaxf(d, 1e-12f)) : 0.f;
    }
    __syncthreads();
    for (int e = tid; e < EE; e += blockDim.x)
        g_norm[e] = sdinv[ei[e]] * ew[e] * sdinv[ei[EE + e]];
}

__global__ void k_tg(const float* __restrict__ win, const int* __restrict__ ei,
                     const float* __restrict__ tw, const float* __restrict__ tv,
                     const float* __restrict__ tb, const float* __restrict__ emb) {
    __shared__ float s[NN];
    int p = blockIdx.x;
    int base = (p >> 4) * (BB * NN) + (p & 15) * NN;
    int tid = threadIdx.x;
    for (int n = tid; n < NN; n += blockDim.x) s[n] = 0.f;
    __syncthreads();
    for (int e = tid; e < EE; e += blockDim.x)
        atomicAdd(&s[ei[EE + e]], g_norm[e] * win[base + ei[e]]);
    __syncthreads();
    for (int idx = tid; idx < NC; idx += blockDim.x) {
        int n = idx >> 5, c = idx & 31;
        float x = win[base + n];
        float val = geluf(s[n] * tw[c] + x * tv[c] + tb[c]);
        int j = base + n;
        int t2 = j & (TT - 1);
        int rest = j >> 6;
        int n2 = rest % NN, b2 = rest / NN;
        g_Xin[(size_t)(t2 * BB + b2) * NC + n2 * CC + c] = val + emb[n2 * CC + c];
    }
}

// ---------------- NT GEMM via tf32 mma.sync (m16n8k8) ----------------
// block tile 128x128, K-chunk 32; 8 warps in 2(M)x4(N); warp tile 64x32
__device__ __forceinline__ uint32 fbits(float f) {
    uint32 u; asm("mov.b32 %0, %1;" : "=r"(u) : "f"(f)); return u;
}
__global__ void __launch_bounds__(256) k_gemm_nt(int sel, const float* __restrict__ W,
                          const float* __restrict__ b1, const float* __restrict__ b2) {
    const float* A; float* Cc; int K;
    if (sel == 0) { A = g_Xin; Cc = g_G0; K = NC; }
    else          { A = g_hs0 + BB * HH; Cc = g_G1; K = HH; }

    __shared__ __align__(16) float sA[128 * 36];
    __shared__ __align__(16) float sB[128 * 36];
    int tid = threadIdx.x;
    int m0 = blockIdx.y * 128, n0 = blockIdx.x * 128;
    int warp = tid >> 5, lane = tid & 31;
    int wm = warp >> 2, wn = warp & 3;
    int lr = lane >> 2, lc = lane & 3;

    float c[4][4][4];
#pragma unroll
    for (int mt = 0; mt < 4; mt++)
#pragma unroll
        for (int nt = 0; nt < 4; nt++)
#pragma unroll
            for (int q = 0; q < 4; q++) c[mt][nt][q] = 0.f;

    for (int k0 = 0; k0 < K; k0 += 32) {
        __syncthreads();
#pragma unroll
        for (int i = 0; i < 4; i++) {
            int idx = tid + i * 256;
            int r = idx >> 3, cc = (idx & 7) << 2;
            *reinterpret_cast<float4*>(&sA[r * 36 + cc]) =
                *reinterpret_cast<const float4*>(A + (size_t)(m0 + r) * K + k0 + cc);
            *reinterpret_cast<float4*>(&sB[r * 36 + cc]) =
                *reinterpret_cast<const float4*>(W + (size_t)(n0 + r) * K + k0 + cc);
        }
        __syncthreads();
#pragma unroll
        for (int kk = 0; kk < 4; kk++) {
            int kb = kk * 8 + lc;
            uint32 a[4][4], b[4][2];
#pragma unroll
            for (int mt = 0; mt < 4; mt++) {
                const float* ap = sA + (wm * 64 + mt * 16 + lr) * 36 + kb;
                a[mt][0] = fbits(ap[0]);
                a[mt][1] = fbits(ap[8 * 36]);
                a[mt][2] = fbits(ap[4]);
                a[mt][3] = fbits(ap[8 * 36 + 4]);
            }
#pragma unroll
            for (int nt = 0; nt < 4; nt++) {
                const float* bp = sB + (wn * 32 + nt * 8 + lr) * 36 + kb;
                b[nt][0] = fbits(bp[0]);
                b[nt][1] = fbits(bp[4]);
            }
#pragma unroll
            for (int mt = 0; mt < 4; mt++)
#pragma unroll
                for (int nt = 0; nt < 4; nt++) {
                    float* cp = c[mt][nt];
                    asm volatile(
                        "mma.sync.aligned.m16n8k8.row.col.f32.tf32.tf32.f32 "
                        "{%0,%1,%2,%3}, {%4,%5,%6,%7}, {%8,%9}, {%0,%1,%2,%3};"
                        : "+f"(cp[0]), "+f"(cp[1]), "+f"(cp[2]), "+f"(cp[3])
                        : "r"(a[mt][0]), "r"(a[mt][1]), "r"(a[mt][2]), "r"(a[mt][3]),
                          "r"(b[nt][0]), "r"(b[nt][1]));
                }
        }
    }

#pragma unroll
    for (int mt = 0; mt < 4; mt++) {
        int row = m0 + wm * 64 + mt * 16 + lr;
#pragma unroll
        for (int nt = 0; nt < 4; nt++) {
            int col = n0 + wn * 32 + nt * 8 + 2 * lc;
            float bb0 = b1[col] + b2[col];
            float bb1 = b1[col + 1] + b2[col + 1];
            float* p0 = Cc + (size_t)row * G4 + col;
            float* p1 = Cc + (size_t)(row + 8) * G4 + col;
            p0[0] = c[mt][nt][0] + bb0; p0[1] = c[mt][nt][1] + bb1;
            p1[0] = c[mt][nt][2] + bb0; p1[1] = c[mt][nt][3] + bb1;
        }
    }
}

// ---------------- shared LSTM-cell machinery ----------------
__device__ __forceinline__ int growl(int l, int bx) {
    return (l >> 2) * HH + bx * 4 + (l & 3);
}

__device__ __forceinline__ void cell_dot(const float* __restrict__ x, int Kx,
                                         const float* __restrict__ W,
                                         float* sh, int bx, ull acc[2][8]) {
    int tid = threadIdx.x;
    int rp = tid >> 5, bs = (tid >> 4) & 1, ks = tid & 15;
    int b2 = tid >> 4, q = tid & 15;
    for (int k0 = 0; k0 < Kx; k0 += 512) {
        int len = min(512, Kx - k0);
        int m4 = len >> 6;
        __syncthreads();
        for (int m = 0; m < m4; m++)
            reinterpret_cast<float4*>(sh + b2 * 512)[m * 16 + q] =
                reinterpret_cast<const float4*>(x + (size_t)b2 * Kx + k0)[m * 16 + q];
        __syncthreads();
        ull wc[2][16];
#pragma unroll 2
        for (int r = 0; r < 2; r++) {
            const float* wp = W + (size_t)growl(rp * 2 + r, bx) * Kx + k0;
            for (int i = 0; i < m4; i++) {
                const ull* pw = reinterpret_cast<const ull*>(wp + (i * 16 + ks) * 4);
                wc[r][2 * i] = pw[0]; wc[r][2 * i + 1] = pw[1];
            }
        }
#pragma unroll 8
        for (int bl = 0; bl < 8; bl++) {
            const float4* row = reinterpret_cast<const float4*>(sh + (bs * 8 + bl) * 512);
            for (int i = 0; i < m4; i++) {
                float4 hv = row[i * 16 + ks];
                ull h0 = pk2(hv.x, hv.y), h1 = pk2(hv.z, hv.w);
                acc[0][bl] = ffma2(wc[0][2 * i], h0, acc[0][bl]);
                acc[0][bl] = ffma2(wc[0][2 * i + 1], h1, acc[0][bl]);
                acc[1][bl] = ffma2(wc[1][2 * i], h0, acc[1][bl]);
                acc[1][bl] = ffma2(wc[1][2 * i + 1], h1, acc[1][bl]);
            }
        }
    }
}

__device__ __forceinline__ void cell_fin(ull acc[2][8], float* sg, int bx,
                                         const float gpre[4], float& creg,
                                         float* __restrict__ h_out) {
    int tid = threadIdx.x;
    int rp = tid >> 5, bs = (tid >> 4) & 1, ks = tid & 15;
    float v[16];
#pragma unroll
    for (int r = 0; r < 2; r++)
#pragma unroll
        for (int bl = 0; bl < 8; bl++) v[r * 8 + bl] = sum2(acc[r][bl]);
#pragma unroll
    for (int d = 1; d < 16; d <<= 1)
#pragma unroll
        for (int i = 0; i < 16; i++) v[i] += __shfl_xor_sync(0xffffffffu, v[i], d);
    sg[(rp * 2 + (ks >> 3)) * 17 + bs * 8 + (ks & 7)] = v[ks];
    __syncthreads();
    if (tid < 64) {
        int jq = tid >> 4, b = tid & 15;
        float gi = sg[jq * 17 + b] + gpre[0];
        float gf = sg[(4 + jq) * 17 + b] + gpre[1];
        float gg = sg[(8 + jq) * 17 + b] + gpre[2];
        float go = sg[(12 + jq) * 17 + b] + gpre[3];
        float cn = sigmf(gf) * creg + sigmf(gi) * tanhf(gg);
        creg = cn;
        h_out[b * HH + bx * 4 + jq] = sigmf(go) * tanhf(cn);
    }
}

// ---------------- persistent recurrence: Whh in registers ----------------
__global__ void __launch_bounds__(256) k_rec(int layer, const float* __restrict__ Whh) {
    __shared__ float sh[16 * 512];
    __shared__ float sg[16 * 17];
    const float* Gall = (layer == 0) ? g_G0 : g_G1;
    float* hs = (layer == 0) ? g_hs0 : g_hs1;
    unsigned* ctr = &g_barctr[layer];
    int tid = threadIdx.x, bx = blockIdx.x;
    int rp = tid >> 5, bs = (tid >> 4) & 1, ks = tid & 15;

    ull w[2][16];
#pragma unroll 2
    for (int r = 0; r < 2; r++) {
        const float* wp = Whh + (size_t)growl(rp * 2 + r, bx) * HH;
#pragma unroll
        for (int i = 0; i < 8; i++) {
            const ull* pw = reinterpret_cast<const ull*>(wp + (i * 16 + ks) * 4);
            w[r][2 * i] = pw[0]; w[r][2 * i + 1] = pw[1];
        }
    }
    float creg = 0.f;
    unsigned tgt = NBLK;

    for (int t = 0; t < TT; t++) {
        const float* h_in = hs + (size_t)t * BB * HH;
        float gpre[4] = {0.f, 0.f, 0.f, 0.f};
        if (tid < 64) {
            const float* Gt = Gall + (size_t)t * BB * G4 + (tid & 15) * G4 + bx * 4 + (tid >> 4);
            gpre[0] = Gt[0]; gpre[1] = Gt[HH]; gpre[2] = Gt[2 * HH]; gpre[3] = Gt[3 * HH];
        }
        __syncthreads();
#pragma unroll
        for (int i = 0; i < 8; i++)
            reinterpret_cast<float4*>(sh)[tid + i * 256] =
                reinterpret_cast<const float4*>(h_in)[tid + i * 256];
        __syncthreads();

        ull acc[2][8];
#pragma unroll
        for (int bl = 0; bl < 8; bl++) { acc[0][bl] = 0ull; acc[1][bl] = 0ull; }
        const float4* base = reinterpret_cast<const float4*>(sh + (bs * 8) * 512);
#pragma unroll 8
        for (int bl = 0; bl < 8; bl++) {
            const float4* row = base + bl * 128;
#pragma unroll
            for (int i = 0; i < 8; i++) {
                float4 hv = row[i * 16 + ks];
                ull h0 = pk2(hv.x, hv.y), h1 = pk2(hv.z, hv.w);
                acc[0][bl] = ffma2(w[0][2 * i], h0, acc[0][bl]);
                acc[0][bl] = ffma2(w[0][2 * i + 1], h1, acc[0][bl]);
                acc[1][bl] = ffma2(w[1][2 * i], h0, acc[1][bl]);
                acc[1][bl] = ffma2(w[1][2 * i + 1], h1, acc[1][bl]);
            }
        }
        cell_fin(acc, sg, bx, gpre, creg, hs + (size_t)(t + 1) * BB * HH);
        if (t < TT - 1) gbar(ctr, tgt);
    }
}

__global__ void k_copyfin() {
    int i = blockIdx.x * blockDim.x + threadIdx.x;
    if (i < BB * HH) {
        g_dh1s[0][i] = g_hs0[(size_t)TT * BB * HH + i];
        g_dh2s[0][i] = g_hs1[(size_t)TT * BB * HH + i];
    }
}

// ---------------- persistent decoder ----------------
__global__ void __launch_bounds__(256) k_dec(
    const float* __restrict__ Wp, const float* __restrict__ bp,
    const int* __restrict__ ei,
    const float* __restrict__ gw, const float* __restrict__ gv,
    const float* __restrict__ gb, const float* __restrict__ emb,
    const float* __restrict__ c1Wih, const float* __restrict__ c1Whh,
    const float* __restrict__ c1bih, const float* __restrict__ c1bhh,
    const float* __restrict__ c2Wih, const float* __restrict__ c2Whh,
    const float* __restrict__ c2bih, const float* __restrict__ c2bhh,
    float* __restrict__ out)
{
    __shared__ float s_x[16 * 512];
    __shared__ float s_g[16 * 17];
    __shared__ float s_h2[HH];
    __shared__ float s_pred[NN];
    __shared__ float s_ss[NN];
    unsigned* ctr = &g_barctr[2];
    unsigned tgt = NBLK;
    int tid = threadIdx.x, bx = blockIdx.x;

    float c1reg = 0.f, c2reg = 0.f;
    float b1pre[4], b2pre[4];
    if (tid < 64) {
        int jq = tid >> 4, b = tid & 15;
        int idx = b * HH + bx * 4 + jq;
        c1reg = g_hs0[(size_t)TT * BB * HH + idx];
        c2reg = g_hs1[(size_t)TT * BB * HH + idx];
#pragma unroll
        for (int g = 0; g < 4; g++) {
            int row = g * HH + bx * 4 + jq;
            b1pre[g] = c1bih[row] + c1bhh[row];
            b2pre[g] = c2bih[row] + c2bhh[row];
        }
    }

    for (int h = 0; h < HZ; h++) {
        if (bx < BB) {
            const float* h2 = g_dh2s[h];
            for (int i = tid; i < HH; i += 256) s_h2[i] = h2[bx * HH + i];
            for (int i = tid; i < NN; i += 256) s_ss[i] = 0.f;
            __syncthreads();
            for (int n = tid; n < NN; n += 256) {
                const float* wr = Wp + (size_t)n * HH;
                float d0 = 0.f, d1 = 0.f, d2 = 0.f, d3 = 0.f;
#pragma unroll 8
                for (int k = 0; k < HH; k += 4) {
                    float4 wv = *reinterpret_cast<const float4*>(wr + k);
                    d0 += wv.x * s_h2[k]; d1 += wv.y * s_h2[k + 1];
                    d2 += wv.z * s_h2[k + 2]; d3 += wv.w * s_h2[k + 3];
                }
                float d = (d0 + d1) + (d2 + d3) + bp[n];
                s_pred[n] = d;
                out[(bx * NN + n) * HZ + h] = d;
            }
            __syncthreads();
            for (int e = tid; e < EE; e += 256)
                atomicAdd(&s_ss[ei[EE + e]], g_norm[e] * s_pred[ei[e]]);
            __syncthreads();
            for (int idx = tid; idx < NC; idx += 256) {
                int n = idx >> 5, c = idx & 31;
                float val = geluf(s_ss[n] * gw[c] + s_pred[n] * gv[c] + gb[c]);
                g_dxins[h][(size_t)bx * NC + idx] = val + emb[idx];
            }
            __syncthreads();
        }
        gbar(ctr, tgt);
        {
            ull acc[2][8];
#pragma unroll
            for (int bl = 0; bl < 8; bl++) { acc[0][bl] = 0ull; acc[1][bl] = 0ull; }
            cell_dot(g_dxins[h], NC, c1Wih, s_x, bx, acc);
            cell_dot(g_dh1s[h], HH, c1Whh, s_x, bx, acc);
            cell_fin(acc, s_g, bx, b1pre, c1reg, g_dh1s[h + 1]);
        }
        gbar(ctr, tgt);
        {
            ull acc[2][8];
#pragma unroll
            for (int bl = 0; bl < 8; bl++) { acc[0][bl] = 0ull; acc[1][bl] = 0ull; }
            cell_dot(g_dh1s[h + 1], HH, c2Wih, s_x, bx, acc);
            cell_dot(g_dh2s[h], HH, c2Whh, s_x, bx, acc);
            cell_fin(acc, s_g, bx, b2pre, c2reg, g_dh2s[h + 1]);
        }
        if (h < HZ - 1) gbar(ctr, tgt);
    }
}

extern "C" void kernel_launch(void* const* d_in, const int* in_sizes, int n_in,
                              void* d_out, int out_size) {
    const float* window = (const float*)d_in[0];
    const int*   ei     = (const int*)d_in[1];
    const float* ew     = (const float*)d_in[2];
    const float* emb    = (const float*)d_in[3];
    const float* tg_w   = (const float*)d_in[4];
    const float* tg_v   = (const float*)d_in[5];
    const float* tg_b   = (const float*)d_in[6];
    const float* gnn_w  = (const float*)d_in[7];
    const float* gnn_v  = (const float*)d_in[8];
    const float* gnn_b  = (const float*)d_in[9];
    const float* Wih0   = (const float*)d_in[10];
    const float* Whh0   = (const float*)d_in[11];
    const float* bih0   = (const float*)d_in[12];
    const float* bhh0   = (const float*)d_in[13];
    const float* Wih1   = (const float*)d_in[14];
    const float* Whh1   = (const float*)d_in[15];
    const float* bih1   = (const float*)d_in[16];
    const float* bhh1   = (const float*)d_in[17];
    const float* c1Wih  = (const float*)d_in[18];
    const float* c1Whh  = (const float*)d_in[19];
    const float* c1bih  = (const float*)d_in[20];
    const float* c1bhh  = (const float*)d_in[21];
    const float* c2Wih  = (const float*)d_in[22];
    const float* c2Whh  = (const float*)d_in[23];
    const float* c2bih  = (const float*)d_in[24];
    const float* c2bhh  = (const float*)d_in[25];
    const float* Wp     = (const float*)d_in[26];
    const float* bp     = (const float*)d_in[27];
    float* out = (float*)d_out;

    k_zero<<<1, 32>>>();
    k_prep<<<1, 256>>>(ei, ew);
    k_tg<<<TB, 256>>>(window, ei, tg_w, tg_v, tg_b, emb);

    dim3 gg(G4 / 128, TB / 128);
    k_gemm_nt<<<gg, 256>>>(0, Wih0, bih0, bhh0);
    k_rec<<<NBLK, 256>>>(0, Whh0);
    k_gemm_nt<<<gg, 256>>>(1, Wih1, bih1, bhh1);
    k_rec<<<NBLK, 256>>>(1, Whh1);

    k_copyfin<<<32, 256>>>();
    k_dec<<<NBLK, 256>>>(Wp, bp, ei, gnn_w, gnn_v, gnn_b, emb,
                         c1Wih, c1Whh, c1bih, c1bhh,
                         c2Wih, c2Whh, c2bih, c2bhh, out);
    (void)in_sizes; (void)n_in; (void)out_size;
}

// round 9
// speedup vs baseline: 2.3024x; 1.0984x over previous
#include <cuda_runtime.h>
#include <cuda_bf16.h>
#include <math.h>
typedef unsigned long long ull;
typedef unsigned int uint32;

#define NN 100
#define CC 32
#define HH 512
#define TT 64
#define BB 16
#define EE 2000
#define HZ 10
#define NC 3200
#define G4 2048
#define TB 1024
#define NBLK 128

__device__ float g_norm[EE];
__device__ float g_Xin[TB * NC];
__device__ float g_G0[TB * G4];
__device__ float g_G1[TB * G4];
__device__ float g_hs0[(TT + 1) * BB * HH];   // slot 0 stays zero
__device__ float g_hs1[(TT + 1) * BB * HH];
__device__ float g_dh1s[HZ + 1][BB * HH];
__device__ float g_dh2s[HZ + 1][BB * HH];
__device__ float g_dxins[HZ][BB * NC];
__device__ unsigned g_barctr[3];

__device__ __forceinline__ float geluf(float x) {
    return 0.5f * x * (1.0f + erff(x * 0.70710678118654752f));
}
__device__ __forceinline__ float sigmf(float x) { return 1.0f / (1.0f + expf(-x)); }

__device__ __forceinline__ ull pk2(float lo, float hi) {
    ull r; asm("mov.b64 %0, {%1, %2};" : "=l"(r) : "f"(lo), "f"(hi)); return r;
}
__device__ __forceinline__ float2 upk2(ull v) {
    float2 r; asm("mov.b64 {%0, %1}, %2;" : "=f"(r.x), "=f"(r.y) : "l"(v)); return r;
}
__device__ __forceinline__ ull ffma2(ull a, ull b, ull c) {
    ull d; asm("fma.rn.f32x2 %0, %1, %2, %3;" : "=l"(d) : "l"(a), "l"(b), "l"(c));
    return d;
}
__device__ __forceinline__ float sum2(ull v) { float2 u = upk2(v); return u.x + u.y; }

__device__ __forceinline__ void gbar(unsigned* ctr, unsigned& tgt) {
    __threadfence();
    __syncthreads();
    if (threadIdx.x == 0) {
        atomicAdd(ctr, 1u);
        while (*(volatile unsigned*)ctr < tgt) { }
    }
    __syncthreads();
    tgt += NBLK;
}

__global__ void k_zero() {
    int i = blockIdx.x * blockDim.x + threadIdx.x;
    if (i < 3) g_barctr[i] = 0u;
}

__global__ void k_prep(const int* __restrict__ ei, const float* __restrict__ ew) {
    __shared__ float sdeg[NN], sdinv[NN];
    int tid = threadIdx.x;
    for (int n = tid; n < NN; n += blockDim.x) sdeg[n] = 0.f;
    __syncthreads();
    for (int e = tid; e < EE; e += blockDim.x) atomicAdd(&sdeg[ei[EE + e]], ew[e]);
    __syncthreads();
    for (int n = tid; n < NN; n += blockDim.x) {
        float d = sdeg[n];
        sdinv[n] = (d > 0.f) ? rsqrtf(fmaxf(d, 1e-12f)) : 0.f;
    }
    __syncthreads();
    for (int e = tid; e < EE; e += blockDim.x)
        g_norm[e] = sdinv[ei[e]] * ew[e] * sdinv[ei[EE + e]];
}

__global__ void k_tg(const float* __restrict__ win, const int* __restrict__ ei,
                     const float* __restrict__ tw, const float* __restrict__ tv,
                     const float* __restrict__ tb, const float* __restrict__ emb) {
    __shared__ float s[NN];
    int p = blockIdx.x;
    int base = (p >> 4) * (BB * NN) + (p & 15) * NN;
    int tid = threadIdx.x;
    for (int n = tid; n < NN; n += blockDim.x) s[n] = 0.f;
    __syncthreads();
    for (int e = tid; e < EE; e += blockDim.x)
        atomicAdd(&s[ei[EE + e]], g_norm[e] * win[base + ei[e]]);
    __syncthreads();
    for (int idx = tid; idx < NC; idx += blockDim.x) {
        int n = idx >> 5, c = idx & 31;
        float x = win[base + n];
        float val = geluf(s[n] * tw[c] + x * tv[c] + tb[c]);
        int j = base + n;
        int t2 = j & (TT - 1);
        int rest = j >> 6;
        int n2 = rest % NN, b2 = rest / NN;
        g_Xin[(size_t)(t2 * BB + b2) * NC + n2 * CC + c] = val + emb[n2 * CC + c];
    }
}

// ---------------- NT GEMM via bf16x3 mma.sync (m16n8k16) ----------------
// block 128x128, K-chunk 32; 8 warps 2(M)x4(N); warp tile 64x32
// fp32 = bf16_hi + bf16_lo; acc = Ahi*Bhi + Ahi*Blo + Alo*Bhi (fp32 accum)
#define RSTR 20   // smem row stride in 4B words (32 bf16 = 16 words + 4 pad)

__device__ __forceinline__ uint32 cvt2bf(float hi_elem, float lo_elem) {
    // pack: low half = lo_elem(k), high half = hi_elem(k+1)
    uint32 r; asm("cvt.rn.bf16x2.f32 %0, %1, %2;" : "=r"(r) : "f"(hi_elem), "f"(lo_elem));
    return r;
}
__device__ __forceinline__ void split_pair(float x, float y, uint32& hi, uint32& lo) {
    hi = cvt2bf(y, x);
    float hx = __uint_as_float(hi << 16);
    float hy = __uint_as_float(hi & 0xFFFF0000u);
    lo = cvt2bf(y - hy, x - hx);
}
__device__ __forceinline__ void mma_bf16(float* c, const uint32 a[4], const uint32 b[2]) {
    asm volatile(
        "mma.sync.aligned.m16n8k16.row.col.f32.bf16.bf16.f32 "
        "{%0,%1,%2,%3}, {%4,%5,%6,%7}, {%8,%9}, {%0,%1,%2,%3};"
        : "+f"(c[0]), "+f"(c[1]), "+f"(c[2]), "+f"(c[3])
        : "r"(a[0]), "r"(a[1]), "r"(a[2]), "r"(a[3]), "r"(b[0]), "r"(b[1]));
}

__global__ void __launch_bounds__(256) k_gemm_nt(int sel, const float* __restrict__ W,
                          const float* __restrict__ b1, const float* __restrict__ b2) {
    const float* A; float* Cc; int K;
    if (sel == 0) { A = g_Xin; Cc = g_G0; K = NC; }
    else          { A = g_hs0 + BB * HH; Cc = g_G1; K = HH; }

    __shared__ uint32 sAhi[128 * RSTR];
    __shared__ uint32 sAlo[128 * RSTR];
    __shared__ uint32 sBhi[128 * RSTR];
    __shared__ uint32 sBlo[128 * RSTR];

    int tid = threadIdx.x;
    int m0 = blockIdx.y * 128, n0 = blockIdx.x * 128;
    int warp = tid >> 5, lane = tid & 31;
    int wm = warp >> 2, wn = warp & 3;
    int lr = lane >> 2, lc = lane & 3;

    // loader role: idx = tid + i*256 -> row=idx>>3, seg=idx&7 (float4 within K32)
    int lrow = tid >> 3, lseg = tid & 7;

    float c[4][4][4];
#pragma unroll
    for (int mt = 0; mt < 4; mt++)
#pragma unroll
        for (int nt = 0; nt < 4; nt++)
#pragma unroll
            for (int q = 0; q < 4; q++) c[mt][nt][q] = 0.f;

    int nchunk = K >> 5;
    float4 ra[4], rb[4];
    // prefetch chunk 0
#pragma unroll
    for (int i = 0; i < 4; i++) {
        int r = lrow + i * 32;
        ra[i] = *reinterpret_cast<const float4*>(A + (size_t)(m0 + r) * K + lseg * 4);
        rb[i] = *reinterpret_cast<const float4*>(W + (size_t)(n0 + r) * K + lseg * 4);
    }

    for (int ch = 0; ch < nchunk; ch++) {
        __syncthreads();
        // split + store current chunk
#pragma unroll
        for (int i = 0; i < 4; i++) {
            int r = lrow + i * 32;
            int w = r * RSTR + lseg * 2;
            uint32 h0, l0, h1, l1;
            split_pair(ra[i].x, ra[i].y, h0, l0);
            split_pair(ra[i].z, ra[i].w, h1, l1);
            sAhi[w] = h0; sAhi[w + 1] = h1;
            sAlo[w] = l0; sAlo[w + 1] = l1;
            split_pair(rb[i].x, rb[i].y, h0, l0);
            split_pair(rb[i].z, rb[i].w, h1, l1);
            sBhi[w] = h0; sBhi[w + 1] = h1;
            sBlo[w] = l0; sBlo[w + 1] = l1;
        }
        __syncthreads();
        // prefetch next chunk (LDGs overlap the mma work below)
        if (ch + 1 < nchunk) {
            int k0 = (ch + 1) * 32;
#pragma unroll
            for (int i = 0; i < 4; i++) {
                int r = lrow + i * 32;
                ra[i] = *reinterpret_cast<const float4*>(A + (size_t)(m0 + r) * K + k0 + lseg * 4);
                rb[i] = *reinterpret_cast<const float4*>(W + (size_t)(n0 + r) * K + k0 + lseg * 4);
            }
        }
#pragma unroll
        for (int kk = 0; kk < 2; kk++) {
            uint32 bhi[4][2], blo[4][2];
#pragma unroll
            for (int nt = 0; nt < 4; nt++) {
                int w = (wn * 32 + nt * 8 + lr) * RSTR + kk * 8 + lc;
                bhi[nt][0] = sBhi[w]; bhi[nt][1] = sBhi[w + 4];
                blo[nt][0] = sBlo[w]; blo[nt][1] = sBlo[w + 4];
            }
#pragma unroll
            for (int mt = 0; mt < 4; mt++) {
                int w = (wm * 64 + mt * 16 + lr) * RSTR + kk * 8 + lc;
                uint32 ahi[4], alo[4];
                ahi[0] = sAhi[w]; ahi[1] = sAhi[w + 8 * RSTR];
                ahi[2] = sAhi[w + 4]; ahi[3] = sAhi[w + 8 * RSTR + 4];
                alo[0] = sAlo[w]; alo[1] = sAlo[w + 8 * RSTR];
                alo[2] = sAlo[w + 4]; alo[3] = sAlo[w + 8 * RSTR + 4];
#pragma unroll
                for (int nt = 0; nt < 4; nt++) {
                    mma_bf16(c[mt][nt], ahi, bhi[nt]);
                    mma_bf16(c[mt][nt], ahi, blo[nt]);
                    mma_bf16(c[mt][nt], alo, bhi[nt]);
                }
            }
        }
    }

#pragma unroll
    for (int mt = 0; mt < 4; mt++) {
        int row = m0 + wm * 64 + mt * 16 + lr;
#pragma unroll
        for (int nt = 0; nt < 4; nt++) {
            int col = n0 + wn * 32 + nt * 8 + 2 * lc;
            float bb0 = b1[col] + b2[col];
            float bb1 = b1[col + 1] + b2[col + 1];
            float* p0 = Cc + (size_t)row * G4 + col;
            float* p1 = Cc + (size_t)(row + 8) * G4 + col;
            p0[0] = c[mt][nt][0] + bb0; p0[1] = c[mt][nt][1] + bb1;
            p1[0] = c[mt][nt][2] + bb0; p1[1] = c[mt][nt][3] + bb1;
        }
    }
}

// ---------------- shared LSTM-cell machinery ----------------
__device__ __forceinline__ int growl(int l, int bx) {
    return (l >> 2) * HH + bx * 4 + (l & 3);
}

__device__ __forceinline__ void cell_dot(const float* __restrict__ x, int Kx,
                                         const float* __restrict__ W,
                                         float* sh, int bx, ull acc[2][8]) {
    int tid = threadIdx.x;
    int rp = tid >> 5, bs = (tid >> 4) & 1, ks = tid & 15;
    int b2 = tid >> 4, q = tid & 15;
    for (int k0 = 0; k0 < Kx; k0 += 512) {
        int len = min(512, Kx - k0);
        int m4 = len >> 6;
        __syncthreads();
        for (int m = 0; m < m4; m++)
            reinterpret_cast<float4*>(sh + b2 * 512)[m * 16 + q] =
                reinterpret_cast<const float4*>(x + (size_t)b2 * Kx + k0)[m * 16 + q];
        __syncthreads();
        ull wc[2][16];
#pragma unroll 2
        for (int r = 0; r < 2; r++) {
            const float* wp = W + (size_t)growl(rp * 2 + r, bx) * Kx + k0;
            for (int i = 0; i < m4; i++) {
                const ull* pw = reinterpret_cast<const ull*>(wp + (i * 16 + ks) * 4);
                wc[r][2 * i] = pw[0]; wc[r][2 * i + 1] = pw[1];
            }
        }
#pragma unroll 8
        for (int bl = 0; bl < 8; bl++) {
            const float4* row = reinterpret_cast<const float4*>(sh + (bs * 8 + bl) * 512);
            for (int i = 0; i < m4; i++) {
                float4 hv = row[i * 16 + ks];
                ull h0 = pk2(hv.x, hv.y), h1 = pk2(hv.z, hv.w);
                acc[0][bl] = ffma2(wc[0][2 * i], h0, acc[0][bl]);
                acc[0][bl] = ffma2(wc[0][2 * i + 1], h1, acc[0][bl]);
                acc[1][bl] = ffma2(wc[1][2 * i], h0, acc[1][bl]);
                acc[1][bl] = ffma2(wc[1][2 * i + 1], h1, acc[1][bl]);
            }
        }
    }
}

__device__ __forceinline__ void cell_fin(ull acc[2][8], float* sg, int bx,
                                         const float gpre[4], float& creg,
                                         float* __restrict__ h_out) {
    int tid = threadIdx.x;
    int rp = tid >> 5, bs = (tid >> 4) & 1, ks = tid & 15;
    float v[16];
#pragma unroll
    for (int r = 0; r < 2; r++)
#pragma unroll
        for (int bl = 0; bl < 8; bl++) v[r * 8 + bl] = sum2(acc[r][bl]);
#pragma unroll
    for (int d = 1; d < 16; d <<= 1)
#pragma unroll
        for (int i = 0; i < 16; i++) v[i] += __shfl_xor_sync(0xffffffffu, v[i], d);
    sg[(rp * 2 + (ks >> 3)) * 17 + bs * 8 + (ks & 7)] = v[ks];
    __syncthreads();
    if (tid < 64) {
        int jq = tid >> 4, b = tid & 15;
        float gi = sg[jq * 17 + b] + gpre[0];
        float gf = sg[(4 + jq) * 17 + b] + gpre[1];
        float gg = sg[(8 + jq) * 17 + b] + gpre[2];
        float go = sg[(12 + jq) * 17 + b] + gpre[3];
        float cn = sigmf(gf) * creg + sigmf(gi) * tanhf(gg);
        creg = cn;
        h_out[b * HH + bx * 4 + jq] = sigmf(go) * tanhf(cn);
    }
}

// ---------------- persistent recurrence: Whh in registers ----------------
__global__ void __launch_bounds__(256) k_rec(int layer, const float* __restrict__ Whh) {
    __shared__ float sh[16 * 512];
    __shared__ float sg[16 * 17];
    const float* Gall = (layer == 0) ? g_G0 : g_G1;
    float* hs = (layer == 0) ? g_hs0 : g_hs1;
    unsigned* ctr = &g_barctr[layer];
    int tid = threadIdx.x, bx = blockIdx.x;
    int rp = tid >> 5, bs = (tid >> 4) & 1, ks = tid & 15;

    ull w[2][16];
#pragma unroll 2
    for (int r = 0; r < 2; r++) {
        const float* wp = Whh + (size_t)growl(rp * 2 + r, bx) * HH;
#pragma unroll
        for (int i = 0; i < 8; i++) {
            const ull* pw = reinterpret_cast<const ull*>(wp + (i * 16 + ks) * 4);
            w[r][2 * i] = pw[0]; w[r][2 * i + 1] = pw[1];
        }
    }
    float creg = 0.f;
    unsigned tgt = NBLK;

    for (int t = 0; t < TT; t++) {
        const float* h_in = hs + (size_t)t * BB * HH;
        float gpre[4] = {0.f, 0.f, 0.f, 0.f};
        if (tid < 64) {
            const float* Gt = Gall + (size_t)t * BB * G4 + (tid & 15) * G4 + bx * 4 + (tid >> 4);
            gpre[0] = Gt[0]; gpre[1] = Gt[HH]; gpre[2] = Gt[2 * HH]; gpre[3] = Gt[3 * HH];
        }
        __syncthreads();
#pragma unroll
        for (int i = 0; i < 8; i++)
            reinterpret_cast<float4*>(sh)[tid + i * 256] =
                reinterpret_cast<const float4*>(h_in)[tid + i * 256];
        __syncthreads();

        ull acc[2][8];
#pragma unroll
        for (int bl = 0; bl < 8; bl++) { acc[0][bl] = 0ull; acc[1][bl] = 0ull; }
        const float4* base = reinterpret_cast<const float4*>(sh + (bs * 8) * 512);
#pragma unroll 8
        for (int bl = 0; bl < 8; bl++) {
            const float4* row = base + bl * 128;
#pragma unroll
            for (int i = 0; i < 8; i++) {
                float4 hv = row[i * 16 + ks];
                ull h0 = pk2(hv.x, hv.y), h1 = pk2(hv.z, hv.w);
                acc[0][bl] = ffma2(w[0][2 * i], h0, acc[0][bl]);
                acc[0][bl] = ffma2(w[0][2 * i + 1], h1, acc[0][bl]);
                acc[1][bl] = ffma2(w[1][2 * i], h0, acc[1][bl]);
                acc[1][bl] = ffma2(w[1][2 * i + 1], h1, acc[1][bl]);
            }
        }
        cell_fin(acc, sg, bx, gpre, creg, hs + (size_t)(t + 1) * BB * HH);
        if (t < TT - 1) gbar(ctr, tgt);
    }
}

__global__ void k_copyfin() {
    int i = blockIdx.x * blockDim.x + threadIdx.x;
    if (i < BB * HH) {
        g_dh1s[0][i] = g_hs0[(size_t)TT * BB * HH + i];
        g_dh2s[0][i] = g_hs1[(size_t)TT * BB * HH + i];
    }
}

// ---------------- persistent decoder ----------------
__global__ void __launch_bounds__(256) k_dec(
    const float* __restrict__ Wp, const float* __restrict__ bp,
    const int* __restrict__ ei,
    const float* __restrict__ gw, const float* __restrict__ gv,
    const float* __restrict__ gb, const float* __restrict__ emb,
    const float* __restrict__ c1Wih, const float* __restrict__ c1Whh,
    const float* __restrict__ c1bih, const float* __restrict__ c1bhh,
    const float* __restrict__ c2Wih, const float* __restrict__ c2Whh,
    const float* __restrict__ c2bih, const float* __restrict__ c2bhh,
    float* __restrict__ out)
{
    __shared__ float s_x[16 * 512];
    __shared__ float s_g[16 * 17];
    __shared__ float s_h2[HH];
    __shared__ float s_pred[NN];
    __shared__ float s_ss[NN];
    unsigned* ctr = &g_barctr[2];
    unsigned tgt = NBLK;
    int tid = threadIdx.x, bx = blockIdx.x;

    float c1reg = 0.f, c2reg = 0.f;
    float b1pre[4], b2pre[4];
    if (tid < 64) {
        int jq = tid >> 4, b = tid & 15;
        int idx = b * HH + bx * 4 + jq;
        c1reg = g_hs0[(size_t)TT * BB * HH + idx];
        c2reg = g_hs1[(size_t)TT * BB * HH + idx];
#pragma unroll
        for (int g = 0; g < 4; g++) {
            int row = g * HH + bx * 4 + jq;
            b1pre[g] = c1bih[row] + c1bhh[row];
            b2pre[g] = c2bih[row] + c2bhh[row];
        }
    }

    for (int h = 0; h < HZ; h++) {
        if (bx < BB) {
            const float* h2 = g_dh2s[h];
            for (int i = tid; i < HH; i += 256) s_h2[i] = h2[bx * HH + i];
            for (int i = tid; i < NN; i += 256) s_ss[i] = 0.f;
            __syncthreads();
            for (int n = tid; n < NN; n += 256) {
                const float* wr = Wp + (size_t)n * HH;
                float d0 = 0.f, d1 = 0.f, d2 = 0.f, d3 = 0.f;
#pragma unroll 8
                for (int k = 0; k < HH; k += 4) {
                    float4 wv = *reinterpret_cast<const float4*>(wr + k);
                    d0 += wv.x * s_h2[k]; d1 += wv.y * s_h2[k + 1];
                    d2 += wv.z * s_h2[k + 2]; d3 += wv.w * s_h2[k + 3];
                }
                float d = (d0 + d1) + (d2 + d3) + bp[n];
                s_pred[n] = d;
                out[(bx * NN + n) * HZ + h] = d;
            }
            __syncthreads();
            for (int e = tid; e < EE; e += 256)
                atomicAdd(&s_ss[ei[EE + e]], g_norm[e] * s_pred[ei[e]]);
            __syncthreads();
            for (int idx = tid; idx < NC; idx += 256) {
                int n = idx >> 5, c = idx & 31;
                float val = geluf(s_ss[n] * gw[c] + s_pred[n] * gv[c] + gb[c]);
                g_dxins[h][(size_t)bx * NC + idx] = val + emb[idx];
            }
            __syncthreads();
        }
        gbar(ctr, tgt);
        {
            ull acc[2][8];
#pragma unroll
            for (int bl = 0; bl < 8; bl++) { acc[0][bl] = 0ull; acc[1][bl] = 0ull; }
            cell_dot(g_dxins[h], NC, c1Wih, s_x, bx, acc);
            cell_dot(g_dh1s[h], HH, c1Whh, s_x, bx, acc);
            cell_fin(acc, s_g, bx, b1pre, c1reg, g_dh1s[h + 1]);
        }
        gbar(ctr, tgt);
        {
            ull acc[2][8];
#pragma unroll
            for (int bl = 0; bl < 8; bl++) { acc[0][bl] = 0ull; acc[1][bl] = 0ull; }
            cell_dot(g_dh1s[h + 1], HH, c2Wih, s_x, bx, acc);
            cell_dot(g_dh2s[h], HH, c2Whh, s_x, bx, acc);
            cell_fin(acc, s_g, bx, b2pre, c2reg, g_dh2s[h + 1]);
        }
        if (h < HZ - 1) gbar(ctr, tgt);
    }
}

extern "C" void kernel_launch(void* const* d_in, const int* in_sizes, int n_in,
                              void* d_out, int out_size) {
    const float* window = (const float*)d_in[0];
    const int*   ei     = (const int*)d_in[1];
    const float* ew     = (const float*)d_in[2];
    const float* emb    = (const float*)d_in[3];
    const float* tg_w   = (const float*)d_in[4];
    const float* tg_v   = (const float*)d_in[5];
    const float* tg_b   = (const float*)d_in[6];
    const float* gnn_w  = (const float*)d_in[7];
    const float* gnn_v  = (const float*)d_in[8];
    const float* gnn_b  = (const float*)d_in[9];
    const float* Wih0   = (const float*)d_in[10];
    const float* Whh0   = (const float*)d_in[11];
    const float* bih0   = (const float*)d_in[12];
    const float* bhh0   = (const float*)d_in[13];
    const float* Wih1   = (const float*)d_in[14];
    const float* Whh1   = (const float*)d_in[15];
    const float* bih1   = (const float*)d_in[16];
    const float* bhh1   = (const float*)d_in[17];
    const float* c1Wih  = (const float*)d_in[18];
    const float* c1Whh  = (const float*)d_in[19];
    const float* c1bih  = (const float*)d_in[20];
    const float* c1bhh  = (const float*)d_in[21];
    const float* c2Wih  = (const float*)d_in[22];
    const float* c2Whh  = (const float*)d_in[23];
    const float* c2bih  = (const float*)d_in[24];
    const float* c2bhh  = (const float*)d_in[25];
    const float* Wp     = (const float*)d_in[26];
    const float* bp     = (const float*)d_in[27];
    float* out = (float*)d_out;

    k_zero<<<1, 32>>>();
    k_prep<<<1, 256>>>(ei, ew);
    k_tg<<<TB, 256>>>(window, ei, tg_w, tg_v, tg_b, emb);

    dim3 gg(G4 / 128, TB / 128);
    k_gemm_nt<<<gg, 256>>>(0, Wih0, bih0, bhh0);
    k_rec<<<NBLK, 256>>>(0, Whh0);
    k_gemm_nt<<<gg, 256>>>(1, Wih1, bih1, bhh1);
    k_rec<<<NBLK, 256>>>(1, Whh1);

    k_copyfin<<<32, 256>>>();
    k_dec<<<NBLK, 256>>>(Wp, bp, ei, gnn_w, gnn_v, gnn_b, emb,
                         c1Wih, c1Whh, c1bih, c1bhh,
                         c2Wih, c2Whh, c2bih, c2bhh, out);
    (void)in_sizes; (void)n_in; (void)out_size;
}